// round 12
// baseline (speedup 1.0000x reference)
#include <cuda_runtime.h>

// GCN 2-layer, padded-bucket CSR pull.
// R11 structure; seg kernels reworked for MLP: 8 lanes/node (2 float4 acc) and
// int4 index loads (bucket is 16B-aligned, padded, unwritten slots read as 0).

#define NMAX 50048
#define CAP  128            // bucket capacity (max in-degree; Poisson(16) -> ~45)

__device__ int g_cnt[NMAX];
__device__ __align__(16) int g_srt[NMAX * CAP + CAP];
__device__ __align__(16) float g_hs1[NMAX * 64];
__device__ __align__(16) float g_h1 [NMAX * 64];
__device__ __align__(16) float g_hs2[NMAX * 16];

// ------------------------------------------------------------------ prep ----
__global__ void k_zero(int N) {
    int i = blockIdx.x * 256 + threadIdx.x;
    if (i < N) g_cnt[i] = 0;
}

__global__ void k_bucket(const int* __restrict__ row, const int* __restrict__ col,
                         int E) {
    int e = blockIdx.x * 256 + threadIdx.x;
    if (e < E) {
        int c = col[e];
        int slot = atomicAdd(&g_cnt[c], 1);
        g_srt[c * CAP + slot] = row[e];
    }
}

// ------------------------------------------------------ GEMM1 + prescale ----
// hs1[n][f] = (x[n,:]@W1[:,f]) * rsqrt(1+cnt[n]).
// 128-node tile, 256 threads, 8 nodes x 4 feats per thread.
__global__ void k_gemm1(const float* __restrict__ x, const float* __restrict__ W,
                        int N) {
    __shared__ float xs[64 * 132];  // xs[k*132 + nloc], nloc 0..127
    int t = threadIdx.x;
    int nbase = blockIdx.x * 128;

#pragma unroll
    for (int i = 0; i < 32; i++) {
        int idx = t + i * 256;                 // 128 nodes x 64 k
        int nl = idx >> 6, k = idx & 63;
        int n = nbase + nl;
        xs[k * 132 + nl] = (n < N) ? x[n * 64 + k] : 0.f;
    }
    __syncthreads();

    int nr = t >> 4;       // nodes 8*nr .. 8*nr+7
    int c  = t & 15;       // feats 4c .. 4c+3
    float acc[8][4];
#pragma unroll
    for (int i = 0; i < 8; i++)
#pragma unroll
        for (int j = 0; j < 4; j++) acc[i][j] = 0.f;

#pragma unroll
    for (int k = 0; k < 64; k++) {
        float4 xa = *(const float4*)&xs[k * 132 + 8 * nr];
        float4 xb = *(const float4*)&xs[k * 132 + 8 * nr + 4];
        float4 wv = __ldg((const float4*)&W[k * 64 + 4 * c]);
        float xv[8] = {xa.x, xa.y, xa.z, xa.w, xb.x, xb.y, xb.z, xb.w};
#pragma unroll
        for (int i = 0; i < 8; i++) {
            acc[i][0] = fmaf(xv[i], wv.x, acc[i][0]);
            acc[i][1] = fmaf(xv[i], wv.y, acc[i][1]);
            acc[i][2] = fmaf(xv[i], wv.z, acc[i][2]);
            acc[i][3] = fmaf(xv[i], wv.w, acc[i][3]);
        }
    }

#pragma unroll
    for (int i = 0; i < 8; i++) {
        int n = nbase + 8 * nr + i;
        if (n < N) {
            float d = rsqrtf(1.f + (float)g_cnt[n]);
            *(float4*)&g_hs1[n * 64 + 4 * c] =
                make_float4(acc[i][0] * d, acc[i][1] * d,
                            acc[i][2] * d, acc[i][3] * d);
        }
    }
}

// ----------------------------------------- segment-sum 1 + finalize + relu ----
// 8 lanes per node, 2 float4 chunks each; int4 index loads; padded-tail safe.
__global__ void k_seg1(const float* __restrict__ b1, int N) {
    int g = blockIdx.x * 256 + threadIdx.x;
    int n = g >> 3;
    int q = g & 7;                 // chunks 2q, 2q+1
    if (n >= N) return;
    int len = g_cnt[n];
    const int4* bu = (const int4*)&g_srt[n * CAP];
    const float4* hs = (const float4*)g_hs1;
    float4 a0 = hs[n * 16 + 2 * q];
    float4 a1 = hs[n * 16 + 2 * q + 1];
    int i = 0;
    for (; i + 3 < len; i += 4) {
        int4 r = bu[i >> 2];
        float4 u0 = hs[r.x * 16 + 2 * q], u1 = hs[r.x * 16 + 2 * q + 1];
        float4 v0 = hs[r.y * 16 + 2 * q], v1 = hs[r.y * 16 + 2 * q + 1];
        float4 w0 = hs[r.z * 16 + 2 * q], w1 = hs[r.z * 16 + 2 * q + 1];
        float4 z0 = hs[r.w * 16 + 2 * q], z1 = hs[r.w * 16 + 2 * q + 1];
        a0.x += (u0.x + v0.x) + (w0.x + z0.x);
        a0.y += (u0.y + v0.y) + (w0.y + z0.y);
        a0.z += (u0.z + v0.z) + (w0.z + z0.z);
        a0.w += (u0.w + v0.w) + (w0.w + z0.w);
        a1.x += (u1.x + v1.x) + (w1.x + z1.x);
        a1.y += (u1.y + v1.y) + (w1.y + z1.y);
        a1.z += (u1.z + v1.z) + (w1.z + z1.z);
        a1.w += (u1.w + v1.w) + (w1.w + z1.w);
    }
    if (i < len) {                               // tail (1-3), padded bucket
        int4 r = bu[i >> 2];
        int rr[3] = {r.x, r.y, r.z};
        int rem = len - i;
#pragma unroll
        for (int j = 0; j < 3; j++) {
            if (j < rem) {
                float4 u0 = hs[rr[j] * 16 + 2 * q];
                float4 u1 = hs[rr[j] * 16 + 2 * q + 1];
                a0.x += u0.x; a0.y += u0.y; a0.z += u0.z; a0.w += u0.w;
                a1.x += u1.x; a1.y += u1.y; a1.z += u1.z; a1.w += u1.w;
            }
        }
    }
    float d = rsqrtf(1.f + (float)len);
    float4 bb0 = ((const float4*)b1)[2 * q];
    float4 bb1 = ((const float4*)b1)[2 * q + 1];
    float4 o0, o1;
    o0.x = fmaxf(fmaf(d, a0.x, bb0.x), 0.f);
    o0.y = fmaxf(fmaf(d, a0.y, bb0.y), 0.f);
    o0.z = fmaxf(fmaf(d, a0.z, bb0.z), 0.f);
    o0.w = fmaxf(fmaf(d, a0.w, bb0.w), 0.f);
    o1.x = fmaxf(fmaf(d, a1.x, bb1.x), 0.f);
    o1.y = fmaxf(fmaf(d, a1.y, bb1.y), 0.f);
    o1.z = fmaxf(fmaf(d, a1.z, bb1.z), 0.f);
    o1.w = fmaxf(fmaf(d, a1.w, bb1.w), 0.f);
    *(float4*)&g_h1[n * 64 + 8 * q]     = o0;
    *(float4*)&g_h1[n * 64 + 8 * q + 4] = o1;
}

// ------------------------------------------------- GEMM2 + dinv prescale ----
__global__ void k_gemm2(const float* __restrict__ W2, int N) {
    __shared__ float ts[64 * 65];    // ts[f*65 + nloc]
    __shared__ float ws[64 * 16];
    int t = threadIdx.x;
    int nbase = blockIdx.x * 64;

    ws[t] = W2[t]; ws[t + 256] = W2[t + 256];
    ws[t + 512] = W2[t + 512]; ws[t + 768] = W2[t + 768];
#pragma unroll
    for (int i = 0; i < 16; i++) {
        int idx = t + i * 256;
        int nl = idx >> 6, f = idx & 63;
        int n = nbase + nl;
        ts[f * 65 + nl] = (n < N) ? g_h1[n * 64 + f] : 0.f;
    }
    __syncthreads();

    int nl = t >> 2;
    int fq = (t & 3) << 2;
    float4 a = make_float4(0.f, 0.f, 0.f, 0.f);
#pragma unroll
    for (int k = 0; k < 64; k++) {
        float xk = ts[k * 65 + nl];
        float4 wv = *(const float4*)&ws[k * 16 + fq];
        a.x = fmaf(xk, wv.x, a.x); a.y = fmaf(xk, wv.y, a.y);
        a.z = fmaf(xk, wv.z, a.z); a.w = fmaf(xk, wv.w, a.w);
    }
    int n = nbase + nl;
    if (n < N) {
        float d = rsqrtf(1.f + (float)g_cnt[n]);
        *(float4*)&g_hs2[n * 16 + fq] =
            make_float4(a.x * d, a.y * d, a.z * d, a.w * d);
    }
}

// --------------------------------- segment-sum 2 + finalize + log_softmax ----
// 4 lanes per node (float4 each); int4 index loads; shfl_xor in aligned quads.
__global__ void k_seg2(const float* __restrict__ b2, float* __restrict__ out,
                       int N) {
    int g = blockIdx.x * 256 + threadIdx.x;
    int n = g >> 2;
    int q = g & 3;
    bool valid = n < N;
    int nc = valid ? n : N - 1;                    // clamp: keep shfl lanes alive
    int len = g_cnt[nc];
    const int4* bu = (const int4*)&g_srt[nc * CAP];
    const float4* hs = (const float4*)g_hs2;
    float4 a = hs[nc * 4 + q];                     // self term
    int i = 0;
    for (; i + 3 < len; i += 4) {
        int4 r = bu[i >> 2];
        float4 v0 = hs[r.x * 4 + q];
        float4 v1 = hs[r.y * 4 + q];
        float4 v2 = hs[r.z * 4 + q];
        float4 v3 = hs[r.w * 4 + q];
        a.x += (v0.x + v1.x) + (v2.x + v3.x);
        a.y += (v0.y + v1.y) + (v2.y + v3.y);
        a.z += (v0.z + v1.z) + (v2.z + v3.z);
        a.w += (v0.w + v1.w) + (v2.w + v3.w);
    }
    if (i < len) {
        int4 r = bu[i >> 2];
        int rr[3] = {r.x, r.y, r.z};
        int rem = len - i;
#pragma unroll
        for (int j = 0; j < 3; j++) {
            if (j < rem) {
                float4 v = hs[rr[j] * 4 + q];
                a.x += v.x; a.y += v.y; a.z += v.z; a.w += v.w;
            }
        }
    }
    float d = rsqrtf(1.f + (float)len);
    float4 bb = ((const float4*)b2)[q];
    float4 v;
    v.x = fmaf(d, a.x, bb.x); v.y = fmaf(d, a.y, bb.y);
    v.z = fmaf(d, a.z, bb.z); v.w = fmaf(d, a.w, bb.w);

    float m = fmaxf(fmaxf(v.x, v.y), fmaxf(v.z, v.w));
    m = fmaxf(m, __shfl_xor_sync(0xffffffffu, m, 1));
    m = fmaxf(m, __shfl_xor_sync(0xffffffffu, m, 2));
    float sm = __expf(v.x - m) + __expf(v.y - m) + __expf(v.z - m) + __expf(v.w - m);
    sm += __shfl_xor_sync(0xffffffffu, sm, 1);
    sm += __shfl_xor_sync(0xffffffffu, sm, 2);
    float ls = __logf(sm);
    if (valid) {
        *(float4*)&out[n * 16 + q * 4] =
            make_float4(v.x - m - ls, v.y - m - ls, v.z - m - ls, v.w - m - ls);
    }
}

// ------------------------------------------------------------------ host ----
extern "C" void kernel_launch(void* const* d_in, const int* in_sizes, int n_in,
                              void* d_out, int out_size) {
    const float* x  = (const float*)d_in[0];
    const int*   ei = (const int*)d_in[1];      // int32 (JAX x64 disabled)
    const float* W1 = (const float*)d_in[2];
    const float* b1 = (const float*)d_in[3];
    const float* W2 = (const float*)d_in[4];
    const float* b2 = (const float*)d_in[5];
    float*       out = (float*)d_out;

    int N = in_sizes[0] / 64;
    int E = in_sizes[1] / 2;
    const int* row = ei;        // sources
    const int* col = ei + E;    // targets

    int gN  = (N + 255) / 256;
    int gE  = (E + 255) / 256;
    int gT  = (N + 127) / 128;        // 128-node tiles
    int gG2 = (N + 63) / 64;          // 64-node tiles
    int gS1 = (N * 8 + 255) / 256;    // 8 lanes/node
    int gS2 = (N * 4 + 255) / 256;    // 4 lanes/node

    k_zero   <<<gN,  256>>>(N);
    k_bucket <<<gE,  256>>>(row, col, E);
    k_gemm1  <<<gT,  256>>>(x, W1, N);
    k_seg1   <<<gS1, 256>>>(b1, N);
    k_gemm2  <<<gG2, 256>>>(W2, N);
    k_seg2   <<<gS2, 256>>>(b2, out, N);
}

// round 13
// speedup vs baseline: 1.1641x; 1.1641x over previous
#include <cuda_runtime.h>

// GCN 2-layer, padded-bucket CSR pull.
// R11 structure (16 lanes/node seg1 — occupancy wins over per-thread ILP),
// plus int4 index loads in both seg kernels.

#define NMAX 50048
#define CAP  128            // bucket capacity (max in-degree; Poisson(16) -> ~45)

__device__ int g_cnt[NMAX];
__device__ __align__(16) int g_srt[NMAX * CAP + CAP];
__device__ __align__(16) float g_hs1[NMAX * 64];
__device__ __align__(16) float g_h1 [NMAX * 64];
__device__ __align__(16) float g_hs2[NMAX * 16];

// ------------------------------------------------------------------ prep ----
__global__ void k_zero(int N) {
    int i = blockIdx.x * 256 + threadIdx.x;
    if (i < N) g_cnt[i] = 0;
}

__global__ void k_bucket(const int* __restrict__ row, const int* __restrict__ col,
                         int E) {
    int e = blockIdx.x * 256 + threadIdx.x;
    if (e < E) {
        int c = col[e];
        int slot = atomicAdd(&g_cnt[c], 1);
        g_srt[c * CAP + slot] = row[e];
    }
}

// ------------------------------------------------------ GEMM1 + prescale ----
// hs1[n][f] = (x[n,:]@W1[:,f]) * rsqrt(1+cnt[n]).
// 128-node tile, 256 threads, 8 nodes x 4 feats per thread.
__global__ void k_gemm1(const float* __restrict__ x, const float* __restrict__ W,
                        int N) {
    __shared__ float xs[64 * 132];  // xs[k*132 + nloc], nloc 0..127
    int t = threadIdx.x;
    int nbase = blockIdx.x * 128;

#pragma unroll
    for (int i = 0; i < 32; i++) {
        int idx = t + i * 256;                 // 128 nodes x 64 k
        int nl = idx >> 6, k = idx & 63;
        int n = nbase + nl;
        xs[k * 132 + nl] = (n < N) ? x[n * 64 + k] : 0.f;
    }
    __syncthreads();

    int nr = t >> 4;       // nodes 8*nr .. 8*nr+7
    int c  = t & 15;       // feats 4c .. 4c+3
    float acc[8][4];
#pragma unroll
    for (int i = 0; i < 8; i++)
#pragma unroll
        for (int j = 0; j < 4; j++) acc[i][j] = 0.f;

#pragma unroll
    for (int k = 0; k < 64; k++) {
        float4 xa = *(const float4*)&xs[k * 132 + 8 * nr];
        float4 xb = *(const float4*)&xs[k * 132 + 8 * nr + 4];
        float4 wv = __ldg((const float4*)&W[k * 64 + 4 * c]);
        float xv[8] = {xa.x, xa.y, xa.z, xa.w, xb.x, xb.y, xb.z, xb.w};
#pragma unroll
        for (int i = 0; i < 8; i++) {
            acc[i][0] = fmaf(xv[i], wv.x, acc[i][0]);
            acc[i][1] = fmaf(xv[i], wv.y, acc[i][1]);
            acc[i][2] = fmaf(xv[i], wv.z, acc[i][2]);
            acc[i][3] = fmaf(xv[i], wv.w, acc[i][3]);
        }
    }

#pragma unroll
    for (int i = 0; i < 8; i++) {
        int n = nbase + 8 * nr + i;
        if (n < N) {
            float d = rsqrtf(1.f + (float)g_cnt[n]);
            *(float4*)&g_hs1[n * 64 + 4 * c] =
                make_float4(acc[i][0] * d, acc[i][1] * d,
                            acc[i][2] * d, acc[i][3] * d);
        }
    }
}

// ----------------------------------------- segment-sum 1 + finalize + relu ----
// 16 lanes per node, one float4 each; int4 index loads; padded-tail safe.
__global__ void k_seg1(const float* __restrict__ b1, int N) {
    int g = blockIdx.x * 256 + threadIdx.x;
    int n = g >> 4;
    int q = g & 15;
    if (n >= N) return;
    int len = g_cnt[n];
    const int4* bu = (const int4*)&g_srt[n * CAP];
    const float4* hs = (const float4*)g_hs1;
    float4 a = hs[n * 16 + q];                     // self term
    int i = 0;
    for (; i + 3 < len; i += 4) {
        int4 r = bu[i >> 2];
        float4 v0 = hs[r.x * 16 + q];
        float4 v1 = hs[r.y * 16 + q];
        float4 v2 = hs[r.z * 16 + q];
        float4 v3 = hs[r.w * 16 + q];
        a.x += (v0.x + v1.x) + (v2.x + v3.x);
        a.y += (v0.y + v1.y) + (v2.y + v3.y);
        a.z += (v0.z + v1.z) + (v2.z + v3.z);
        a.w += (v0.w + v1.w) + (v2.w + v3.w);
    }
    if (i < len) {                                 // tail 1-3 (padded bucket)
        int4 r = bu[i >> 2];
        int rr[3] = {r.x, r.y, r.z};
        int rem = len - i;
#pragma unroll
        for (int j = 0; j < 3; j++) {
            if (j < rem) {
                float4 v = hs[rr[j] * 16 + q];
                a.x += v.x; a.y += v.y; a.z += v.z; a.w += v.w;
            }
        }
    }
    float d = rsqrtf(1.f + (float)len);
    float4 bb = ((const float4*)b1)[q];
    float4 o;
    o.x = fmaxf(fmaf(d, a.x, bb.x), 0.f);
    o.y = fmaxf(fmaf(d, a.y, bb.y), 0.f);
    o.z = fmaxf(fmaf(d, a.z, bb.z), 0.f);
    o.w = fmaxf(fmaf(d, a.w, bb.w), 0.f);
    *(float4*)&g_h1[n * 64 + q * 4] = o;
}

// ------------------------------------------------- GEMM2 + dinv prescale ----
__global__ void k_gemm2(const float* __restrict__ W2, int N) {
    __shared__ float ts[64 * 65];    // ts[f*65 + nloc]
    __shared__ float ws[64 * 16];
    int t = threadIdx.x;
    int nbase = blockIdx.x * 64;

    ws[t] = W2[t]; ws[t + 256] = W2[t + 256];
    ws[t + 512] = W2[t + 512]; ws[t + 768] = W2[t + 768];
#pragma unroll
    for (int i = 0; i < 16; i++) {
        int idx = t + i * 256;
        int nl = idx >> 6, f = idx & 63;
        int n = nbase + nl;
        ts[f * 65 + nl] = (n < N) ? g_h1[n * 64 + f] : 0.f;
    }
    __syncthreads();

    int nl = t >> 2;
    int fq = (t & 3) << 2;
    float4 a = make_float4(0.f, 0.f, 0.f, 0.f);
#pragma unroll
    for (int k = 0; k < 64; k++) {
        float xk = ts[k * 65 + nl];
        float4 wv = *(const float4*)&ws[k * 16 + fq];
        a.x = fmaf(xk, wv.x, a.x); a.y = fmaf(xk, wv.y, a.y);
        a.z = fmaf(xk, wv.z, a.z); a.w = fmaf(xk, wv.w, a.w);
    }
    int n = nbase + nl;
    if (n < N) {
        float d = rsqrtf(1.f + (float)g_cnt[n]);
        *(float4*)&g_hs2[n * 16 + fq] =
            make_float4(a.x * d, a.y * d, a.z * d, a.w * d);
    }
}

// --------------------------------- segment-sum 2 + finalize + log_softmax ----
// 4 lanes per node (float4 each); int4 index loads; shfl_xor in aligned quads.
__global__ void k_seg2(const float* __restrict__ b2, float* __restrict__ out,
                       int N) {
    int g = blockIdx.x * 256 + threadIdx.x;
    int n = g >> 2;
    int q = g & 3;
    bool valid = n < N;
    int nc = valid ? n : N - 1;                    // clamp: keep shfl lanes alive
    int len = g_cnt[nc];
    const int4* bu = (const int4*)&g_srt[nc * CAP];
    const float4* hs = (const float4*)g_hs2;
    float4 a = hs[nc * 4 + q];                     // self term
    int i = 0;
    for (; i + 3 < len; i += 4) {
        int4 r = bu[i >> 2];
        float4 v0 = hs[r.x * 4 + q];
        float4 v1 = hs[r.y * 4 + q];
        float4 v2 = hs[r.z * 4 + q];
        float4 v3 = hs[r.w * 4 + q];
        a.x += (v0.x + v1.x) + (v2.x + v3.x);
        a.y += (v0.y + v1.y) + (v2.y + v3.y);
        a.z += (v0.z + v1.z) + (v2.z + v3.z);
        a.w += (v0.w + v1.w) + (v2.w + v3.w);
    }
    if (i < len) {
        int4 r = bu[i >> 2];
        int rr[3] = {r.x, r.y, r.z};
        int rem = len - i;
#pragma unroll
        for (int j = 0; j < 3; j++) {
            if (j < rem) {
                float4 v = hs[rr[j] * 4 + q];
                a.x += v.x; a.y += v.y; a.z += v.z; a.w += v.w;
            }
        }
    }
    float d = rsqrtf(1.f + (float)len);
    float4 bb = ((const float4*)b2)[q];
    float4 v;
    v.x = fmaf(d, a.x, bb.x); v.y = fmaf(d, a.y, bb.y);
    v.z = fmaf(d, a.z, bb.z); v.w = fmaf(d, a.w, bb.w);

    float m = fmaxf(fmaxf(v.x, v.y), fmaxf(v.z, v.w));
    m = fmaxf(m, __shfl_xor_sync(0xffffffffu, m, 1));
    m = fmaxf(m, __shfl_xor_sync(0xffffffffu, m, 2));
    float sm = __expf(v.x - m) + __expf(v.y - m) + __expf(v.z - m) + __expf(v.w - m);
    sm += __shfl_xor_sync(0xffffffffu, sm, 1);
    sm += __shfl_xor_sync(0xffffffffu, sm, 2);
    float ls = __logf(sm);
    if (valid) {
        *(float4*)&out[n * 16 + q * 4] =
            make_float4(v.x - m - ls, v.y - m - ls, v.z - m - ls, v.w - m - ls);
    }
}

// ------------------------------------------------------------------ host ----
extern "C" void kernel_launch(void* const* d_in, const int* in_sizes, int n_in,
                              void* d_out, int out_size) {
    const float* x  = (const float*)d_in[0];
    const int*   ei = (const int*)d_in[1];      // int32 (JAX x64 disabled)
    const float* W1 = (const float*)d_in[2];
    const float* b1 = (const float*)d_in[3];
    const float* W2 = (const float*)d_in[4];
    const float* b2 = (const float*)d_in[5];
    float*       out = (float*)d_out;

    int N = in_sizes[0] / 64;
    int E = in_sizes[1] / 2;
    const int* row = ei;        // sources
    const int* col = ei + E;    // targets

    int gN  = (N + 255) / 256;
    int gE  = (E + 255) / 256;
    int gT  = (N + 127) / 128;        // 128-node tiles
    int gG2 = (N + 63) / 64;          // 64-node tiles
    int gS1 = (N * 16 + 255) / 256;   // 16 lanes/node
    int gS2 = (N * 4 + 255) / 256;    // 4 lanes/node

    k_zero   <<<gN,  256>>>(N);
    k_bucket <<<gE,  256>>>(row, col, E);
    k_gemm1  <<<gT,  256>>>(x, W1, N);
    k_seg1   <<<gS1, 256>>>(b1, N);
    k_gemm2  <<<gG2, 256>>>(W2, N);
    k_seg2   <<<gS2, 256>>>(b2, out, N);
}